// round 10
// baseline (speedup 1.0000x reference)
#include <cuda_runtime.h>

#define W 256
#define H 256
#define BATCH 64
#define NF 8
#define KS 15
#define PAD 7

#define TILE_X 64           // 16 threads x 4 px
#define TILE_Y 16
#define SROWS (TILE_Y + KS - 1)   // 30
#define SCOLS (TILE_X + KS - 1)   // 78
#define SSTRIDE 80

// derived-weight layout (floats, duplicated for f32x2 broadcast)
#define WQ_COL 784          // 49 quads * 16
#define WQ_ROW 854          // + 7*10
#define WQ_CEN 924          // + 7*10
#define WQ_TOTAL 934

#define CHAN_BLOCKS 1024    // 4 float4-triples per thread
#define N4_STRIDE (CHAN_BLOCKS * 256)     // 262144

typedef unsigned long long ull;

__device__ float g_xs[BATCH * H * W];
__device__ float g_w[KS * KS * NF];    // full weights [tap][filter] (fallback)
__device__ float g_wq[WQ_TOTAL];       // quad-symmetric derived weights
__device__ int   g_flag;               // 1 -> symmetry violated, use fallback

__device__ __forceinline__ ull pk(float a, float b) {
    ull r; asm("mov.b64 %0, {%1, %2};" : "=l"(r) : "f"(a), "f"(b)); return r;
}
__device__ __forceinline__ ull add2(ull a, ull b) {
    ull r; asm("add.rn.f32x2 %0, %1, %2;" : "=l"(r) : "l"(a), "l"(b)); return r;
}
__device__ __forceinline__ ull sub2(ull a, ull b) {
    ull r; asm("sub.rn.f32x2 %0, %1, %2;" : "=l"(r) : "l"(a), "l"(b)); return r;
}
__device__ __forceinline__ void fma2(ull& acc, ull a, ull b) {
    asm("fma.rn.f32x2 %0, %1, %2, %0;" : "+l"(acc) : "l"(a), "l"(b));
}
__device__ __forceinline__ void unpk(float& lo, float& hi, ull v) {
    asm("mov.b64 {%0, %1}, %2;" : "=f"(lo), "=f"(hi) : "l"(v));
}

// ---------------------------------------------------------------------------
// Prep: blocks [0, CHAN_BLOCKS) channel-sum (4 float4s/thread, MLP~12);
// block CHAN_BLOCKS builds the Gabor + derived weights.
// ---------------------------------------------------------------------------
__global__ void prep_kernel(const float* __restrict__ x,
                            const float* __restrict__ theta,
                            const float* __restrict__ sigma,
                            const float* __restrict__ lambd,
                            const float* __restrict__ gamma,
                            const float* __restrict__ psi) {
    if (blockIdx.x < CHAN_BLOCKS) {
        const int plane4 = H * W / 4;
        int g0 = blockIdx.x * blockDim.x + threadIdx.x;
        #pragma unroll
        for (int k = 0; k < 4; k++) {
            int i = g0 + k * N4_STRIDE;
            int b = i / plane4;
            int p = i - b * plane4;
            const float4* xb = (const float4*)x + (size_t)b * 3 * plane4;
            float4 a = __ldg(xb + p);
            float4 c = __ldg(xb + p + plane4);
            float4 d = __ldg(xb + p + 2 * plane4);
            float4 r;
            r.x = a.x + c.x + d.x;
            r.y = a.y + c.y + d.y;
            r.z = a.z + c.z + d.z;
            r.w = a.w + c.w + d.w;
            ((float4*)g_xs)[i] = r;
        }
        return;
    }

    // ---- Gabor weights ----
    __shared__ float s_w[NF][228];
    __shared__ int sflag;
    int tid = threadIdx.x;
    int warp = tid >> 5;
    int lane = tid & 31;
    if (tid == 0) sflag = 0;

    if (warp < NF) {
        int f = warp;
        float th = theta[f];
        float sg = fmaxf(sigma[f], 1.0f);
        float lb = fmaxf(lambd[f], 2.0f);
        float gm = fminf(fmaxf(gamma[f], 0.1f), 1.0f);
        float ps = psi[f];
        float ct = cosf(th), st = sinf(th);
        const float TWO_PI = 6.283185307179586f;
        float inv_sg2 = 1.0f / (sg * sg);
        float gm2 = gm * gm;

        float vals[8];
        float sum = 0.0f;
        #pragma unroll
        for (int k = 0; k < 8; k++) {
            int i = lane + 32 * k;
            float v = 0.0f;
            if (i < KS * KS) {
                int hh = i / KS, ww = i % KS;
                float y = (float)(hh - PAD);
                float xx = (float)(ww - PAD);
                float xt = xx * ct + y * st;
                float yt = -xx * st + y * ct;
                float gaussian = expf(-0.5f * (xt * xt + gm2 * yt * yt) * inv_sg2);
                float sinus = cosf(TWO_PI * xt / lb + ps);
                v = gaussian * sinus;
            }
            vals[k] = v;
            sum += v;
        }
        #pragma unroll
        for (int o = 16; o; o >>= 1) sum += __shfl_xor_sync(0xffffffffu, sum, o);
        float mean = sum * (1.0f / 225.0f);

        float ss = 0.0f;
        #pragma unroll
        for (int k = 0; k < 8; k++) {
            int i = lane + 32 * k;
            if (i < KS * KS) {
                float d = vals[k] - mean;
                ss += d * d;
            }
        }
        #pragma unroll
        for (int o = 16; o; o >>= 1) ss += __shfl_xor_sync(0xffffffffu, ss, o);
        float inv = 1.0f / (sqrtf(ss * (1.0f / 224.0f)) + 1e-8f);

        #pragma unroll
        for (int k = 0; k < 8; k++) {
            int i = lane + 32 * k;
            if (i < KS * KS) s_w[f][i] = (vals[k] - mean) * inv;
        }
    }
    __syncthreads();

    for (int idx = tid; idx < KS * KS * NF; idx += 256) {
        int i = idx >> 3, f = idx & 7;
        g_w[idx] = s_w[f][i];
    }

    const int gf[5] = {0, 1, 2, 3, 4};
    const int gp[5] = {0, 7, 6, 5, 4};
    const float E = 1e-5f;
    int bad = 0;

    for (int idx = tid; idx < 245; idx += 256) {
        int q = idx / 5, g = idx % 5;
        int kyp = q / 7, kxp = q % 7;
        int i1 = kyp * 15 + kxp;
        int i2 = (14 - kyp) * 15 + (14 - kxp);
        int i3 = kyp * 15 + (14 - kxp);
        int i4 = (14 - kyp) * 15 + kxp;
        int f = gf[g], fp = gp[g];
        float f1 = s_w[f][i1], f2 = s_w[f][i2], f3 = s_w[f][i3], f4 = s_w[f][i4];
        float p1 = s_w[fp][i1], p2 = s_w[fp][i2], p3 = s_w[fp][i3], p4 = s_w[fp][i4];
        float af = 0.5f * (f1 + f2), bf = 0.5f * (f3 + f4);
        float ap = 0.5f * (p1 + p2), bp = 0.5f * (p3 + p4);
        float wpf = 0.5f * (af + bf), wmf = 0.5f * (af - bf);
        float wpp = 0.5f * (ap + bp), wmp = 0.5f * (ap - bp);
        float wp = 0.5f * (wpf + wpp), wm = 0.5f * (wmf - wmp);
        if (fabsf(f1 - f2) > E || fabsf(f3 - f4) > E ||
            fabsf(p1 - p2) > E || fabsf(p3 - p4) > E ||
            fabsf(wpf - wpp) > E || fabsf(wmf + wmp) > E) bad = 1;
        g_wq[q * 16 + 2 * g] = wp;
        g_wq[q * 16 + 2 * g + 1] = wp;
        if (g >= 1 && g <= 3) {
            g_wq[q * 16 + 10 + 2 * (g - 1)] = wm;
            g_wq[q * 16 + 10 + 2 * (g - 1) + 1] = wm;
        }
    }

    for (int idx = tid; idx < 35; idx += 256) {
        int kyp = idx / 5, g = idx % 5;
        int i1 = kyp * 15 + 7, i2 = (14 - kyp) * 15 + 7;
        int f = gf[g], fp = gp[g];
        float f1 = s_w[f][i1], f2 = s_w[f][i2];
        float p1 = s_w[fp][i1], p2 = s_w[fp][i2];
        float af = 0.5f * (f1 + f2), ap = 0.5f * (p1 + p2);
        float wp = 0.5f * (af + ap);
        if (fabsf(f1 - f2) > E || fabsf(p1 - p2) > E || fabsf(af - ap) > E) bad = 1;
        g_wq[WQ_COL + kyp * 10 + 2 * g] = wp;
        g_wq[WQ_COL + kyp * 10 + 2 * g + 1] = wp;
    }

    for (int idx = tid; idx < 35; idx += 256) {
        int kxp = idx / 5, g = idx % 5;
        int i1 = 105 + kxp, i3 = 105 + 14 - kxp;
        int f = gf[g], fp = gp[g];
        float f1 = s_w[f][i1], f3 = s_w[f][i3];
        float p1 = s_w[fp][i1], p3 = s_w[fp][i3];
        float af = 0.5f * (f1 + f3), ap = 0.5f * (p1 + p3);
        float wp = 0.5f * (af + ap);
        if (fabsf(f1 - f3) > E || fabsf(p1 - p3) > E || fabsf(af - ap) > E) bad = 1;
        g_wq[WQ_ROW + kxp * 10 + 2 * g] = wp;
        g_wq[WQ_ROW + kxp * 10 + 2 * g + 1] = wp;
    }

    if (tid < 5) {
        int g = tid;
        int f = gf[g], fp = gp[g];
        float f1 = s_w[f][112], p1 = s_w[fp][112];
        float wp = 0.5f * (f1 + p1);
        if (fabsf(f1 - p1) > E) bad = 1;
        g_wq[WQ_CEN + 2 * g] = wp;
        g_wq[WQ_CEN + 2 * g + 1] = wp;
    }

    if (bad) atomicOr(&sflag, 1);
    __syncthreads();
    if (tid == 0) g_flag = sflag;
}

// ---------------------------------------------------------------------------
// Conv: 4-fold symmetry, shifted packed windows, SHARED-memory weights
// (LDS broadcast, floor 2-4 cyc vs LDC floor 8).
// Block (16,16), tile 64x16, 4 px/thread, 3 CTA/SM.
// ---------------------------------------------------------------------------
__global__ void __launch_bounds__(256, 3)
gabor_conv_sym(float* __restrict__ out) {
    __shared__ __align__(16) float s_in[SROWS * SSTRIDE];
    __shared__ __align__(16) float s_wq[WQ_TOTAL + 2];

    int txq = threadIdx.x;        // 0..15 -> 4 px each
    int tyr = threadIdx.y;        // 0..15
    int tid = txq + tyr * 16;
    int x0 = blockIdx.x * TILE_X;
    int y0 = blockIdx.y * TILE_Y;
    int b  = blockIdx.z;

    if (g_flag != 0) {
        // generic correct path (runs only if symmetry check failed)
        const float* xs = g_xs + (size_t)b * H * W;
        float* ob = out + (size_t)b * NF * H * W;
        int y = y0 + tyr;
        #pragma unroll 1
        for (int f = 0; f < NF; f++) {
            #pragma unroll 1
            for (int p = 0; p < 4; p++) {
                int px = x0 + txq * 4 + p;
                float acc = 0.0f;
                for (int ky = 0; ky < KS; ky++) {
                    int gy = y - PAD + ky;
                    if (gy < 0 || gy >= H) continue;
                    for (int kx = 0; kx < KS; kx++) {
                        int gx = px - PAD + kx;
                        if (gx < 0 || gx >= W) continue;
                        acc += g_w[(ky * KS + kx) * NF + f] * xs[gy * W + gx];
                    }
                }
                ob[f * H * W + y * W + px] = acc;
            }
        }
        return;
    }

    // load weights into shared (broadcast-read later)
    for (int i = tid; i < WQ_TOTAL; i += 256) s_wq[i] = g_wq[i];

    const float* xs = g_xs + (size_t)b * H * W;
    for (int i = tid; i < SROWS * SCOLS; i += 256) {
        int r = i / SCOLS, c = i - r * SCOLS;
        int gy = y0 - PAD + r;
        int gx = x0 - PAD + c;
        float v = 0.0f;
        if (gy >= 0 && gy < H && gx >= 0 && gx < W) v = xs[gy * W + gx];
        s_in[r * SSTRIDE + c] = v;
    }
    __syncthreads();

    int c0 = txq * 4;
    ull P[5][2], Q[3][2];
    #pragma unroll
    for (int g = 0; g < 5; g++) { P[g][0] = 0ull; P[g][1] = 0ull; }
    #pragma unroll
    for (int g = 0; g < 3; g++) { Q[g][0] = 0ull; Q[g][1] = 0ull; }

    #pragma unroll 1
    for (int kyp = 0; kyp < 7; kyp++) {
        const float4* tp = (const float4*)(s_in + (tyr + kyp) * SSTRIDE + c0);
        const float4* bp = (const float4*)(s_in + (tyr + 14 - kyp) * SSTRIDE + c0);

        // packed shifted windows
        ull tbP[17], tdP[17];
        #pragma unroll
        for (int j = 0; j < 5; j++) {
            float4 tv = tp[j];
            float4 bv = bp[j];
            ull t0 = pk(tv.x, tv.y), t1 = pk(tv.z, tv.w);
            ull b0 = pk(bv.x, bv.y), b1 = pk(bv.z, bv.w);
            tbP[4 * j] = add2(t0, b0);
            tdP[4 * j] = sub2(t0, b0);
            if (4 * j + 2 <= 16) {
                tbP[4 * j + 2] = add2(t1, b1);
                tdP[4 * j + 2] = sub2(t1, b1);
            }
        }
        #pragma unroll
        for (int k = 0; k < 8; k++) {
            float l0, h0, l1, h1;
            unpk(l0, h0, tbP[2 * k]); unpk(l1, h1, tbP[2 * k + 2]);
            tbP[2 * k + 1] = pk(h0, l1);
            unpk(l0, h0, tdP[2 * k]); unpk(l1, h1, tdP[2 * k + 2]);
            tdP[2 * k + 1] = pk(h0, l1);
        }

        const float* wq = s_wq + kyp * 112;
        #pragma unroll
        for (int kxp = 0; kxp < 7; kxp++) {
            const ulonglong2* wv2 = (const ulonglong2*)(wq + kxp * 16);
            ulonglong2 wa = wv2[0], wb = wv2[1], wc2 = wv2[2], wd = wv2[3];
            ull w0 = wa.x, w1 = wa.y, w2 = wb.x, w3 = wb.y, w4 = wc2.x;
            ull m0 = wc2.y, m1 = wd.x, m2 = wd.y;
            #pragma unroll
            for (int pp = 0; pp < 2; pp++) {
                int o = 2 * pp;
                ull u = add2(tbP[o + kxp], tbP[o + 14 - kxp]);
                ull v = sub2(tdP[o + kxp], tdP[o + 14 - kxp]);
                fma2(P[0][pp], u, w0);
                fma2(P[1][pp], u, w1);
                fma2(P[2][pp], u, w2);
                fma2(P[3][pp], u, w3);
                fma2(P[4][pp], u, w4);
                fma2(Q[0][pp], v, m0);
                fma2(Q[1][pp], v, m1);
                fma2(Q[2][pp], v, m2);
            }
        }
        const ull* wc = (const ull*)(s_wq + WQ_COL + kyp * 10);
        ull c0w = wc[0], c1w = wc[1], c2w = wc[2], c3w = wc[3], c4w = wc[4];
        #pragma unroll
        for (int pp = 0; pp < 2; pp++) {
            ull u = tbP[2 * pp + 7];
            fma2(P[0][pp], u, c0w);
            fma2(P[1][pp], u, c1w);
            fma2(P[2][pp], u, c2w);
            fma2(P[3][pp], u, c3w);
            fma2(P[4][pp], u, c4w);
        }
    }

    // ky = 7 row
    {
        const float4* rp = (const float4*)(s_in + (tyr + 7) * SSTRIDE + c0);
        ull rP[17];
        float rf[20];
        #pragma unroll
        for (int j = 0; j < 5; j++) {
            float4 v = rp[j];
            rf[4 * j + 0] = v.x; rf[4 * j + 1] = v.y;
            rf[4 * j + 2] = v.z; rf[4 * j + 3] = v.w;
        }
        #pragma unroll
        for (int i = 0; i < 17; i++) rP[i] = pk(rf[i], rf[i + 1]);

        #pragma unroll
        for (int kxp = 0; kxp < 7; kxp++) {
            const ull* wr = (const ull*)(s_wq + WQ_ROW + kxp * 10);
            ull r0w = wr[0], r1w = wr[1], r2w = wr[2], r3w = wr[3], r4w = wr[4];
            #pragma unroll
            for (int pp = 0; pp < 2; pp++) {
                int o = 2 * pp;
                ull u = add2(rP[o + kxp], rP[o + 14 - kxp]);
                fma2(P[0][pp], u, r0w);
                fma2(P[1][pp], u, r1w);
                fma2(P[2][pp], u, r2w);
                fma2(P[3][pp], u, r3w);
                fma2(P[4][pp], u, r4w);
            }
        }
        const ull* wn = (const ull*)(s_wq + WQ_CEN);
        ull n0 = wn[0], n1 = wn[1], n2 = wn[2], n3 = wn[3], n4 = wn[4];
        #pragma unroll
        for (int pp = 0; pp < 2; pp++) {
            ull u = rP[2 * pp + 7];
            fma2(P[0][pp], u, n0);
            fma2(P[1][pp], u, n1);
            fma2(P[2][pp], u, n2);
            fma2(P[3][pp], u, n3);
            fma2(P[4][pp], u, n4);
        }
    }

    // epilogue
    float p[5][4], q[3][4];
    #pragma unroll
    for (int g = 0; g < 5; g++) {
        unpk(p[g][0], p[g][1], P[g][0]);
        unpk(p[g][2], p[g][3], P[g][1]);
    }
    #pragma unroll
    for (int g = 0; g < 3; g++) {
        unpk(q[g][0], q[g][1], Q[g][0]);
        unpk(q[g][2], q[g][3], Q[g][1]);
    }

    float r[8][4];
    #pragma unroll
    for (int px = 0; px < 4; px++) {
        r[0][px] = p[0][px];
        r[4][px] = p[4][px];
        r[1][px] = p[1][px] + q[0][px];
        r[7][px] = p[1][px] - q[0][px];
        r[2][px] = p[2][px] + q[1][px];
        r[6][px] = p[2][px] - q[1][px];
        r[3][px] = p[3][px] + q[2][px];
        r[5][px] = p[3][px] - q[2][px];
    }

    float* ob = out + (size_t)b * NF * H * W;
    int y = y0 + tyr;
    int xb = x0 + c0;
    #pragma unroll
    for (int f = 0; f < NF; f++) {
        float4 v = make_float4(r[f][0], r[f][1], r[f][2], r[f][3]);
        *(float4*)(ob + f * H * W + y * W + xb) = v;
    }
}

// ---------------------------------------------------------------------------
extern "C" void kernel_launch(void* const* d_in, const int* in_sizes, int n_in,
                              void* d_out, int out_size) {
    const float* x     = (const float*)d_in[0];
    const float* theta = (const float*)d_in[1];
    const float* sigma = (const float*)d_in[2];
    const float* lambd = (const float*)d_in[3];
    const float* gamma = (const float*)d_in[4];
    const float* psi   = (const float*)d_in[5];
    float* out = (float*)d_out;

    prep_kernel<<<CHAN_BLOCKS + 1, 256>>>(x, theta, sigma, lambd, gamma, psi);

    dim3 blk(16, 16);
    dim3 grd(W / TILE_X, H / TILE_Y, BATCH);
    gabor_conv_sym<<<grd, blk>>>(out);
}

// round 11
// speedup vs baseline: 1.2436x; 1.2436x over previous
#include <cuda_runtime.h>

#define W 256
#define H 256
#define BATCH 64
#define NF 8
#define KS 15
#define PAD 7

#define TILE_X 64           // 16 threads x 4 px
#define TILE_Y 16
#define SROWS (TILE_Y + KS - 1)   // 30
#define SCOLS (TILE_X + KS - 1)   // 78
#define SSTRIDE 80

// derived-weight layout (floats, duplicated for f32x2 broadcast)
#define WQ_COL 784          // 49 quads * 16
#define WQ_ROW 854          // + 7*10
#define WQ_CEN 924          // + 7*10
#define WQ_TOTAL 934

#define CHAN_BLOCKS 1024    // 4 float4-triples per thread
#define N4_STRIDE (CHAN_BLOCKS * 256)     // 262144

typedef unsigned long long ull;

__device__ float g_xs[BATCH * H * W];
__device__ float g_w[KS * KS * NF];    // full weights [tap][filter] (fallback)
__device__ float g_wq[WQ_TOTAL];       // staging for constant copy
__device__ int   g_flag;               // 1 -> symmetry violated, use fallback

__constant__ __align__(16) float c_wq[WQ_TOTAL];

__device__ __forceinline__ ull pk(float a, float b) {
    ull r; asm("mov.b64 %0, {%1, %2};" : "=l"(r) : "f"(a), "f"(b)); return r;
}
__device__ __forceinline__ ull add2(ull a, ull b) {
    ull r; asm("add.rn.f32x2 %0, %1, %2;" : "=l"(r) : "l"(a), "l"(b)); return r;
}
__device__ __forceinline__ ull sub2(ull a, ull b) {
    ull r; asm("sub.rn.f32x2 %0, %1, %2;" : "=l"(r) : "l"(a), "l"(b)); return r;
}
__device__ __forceinline__ void fma2(ull& acc, ull a, ull b) {
    asm("fma.rn.f32x2 %0, %1, %2, %0;" : "+l"(acc) : "l"(a), "l"(b));
}
__device__ __forceinline__ void unpk(float& lo, float& hi, ull v) {
    asm("mov.b64 {%0, %1}, %2;" : "=f"(lo), "=f"(hi) : "l"(v));
}

// ---------------------------------------------------------------------------
// Prep: blocks [0, CHAN_BLOCKS) channel-sum (4 float4s/thread, MLP~12);
// block CHAN_BLOCKS builds the Gabor + derived weights.
// ---------------------------------------------------------------------------
__global__ void prep_kernel(const float* __restrict__ x,
                            const float* __restrict__ theta,
                            const float* __restrict__ sigma,
                            const float* __restrict__ lambd,
                            const float* __restrict__ gamma,
                            const float* __restrict__ psi) {
    if (blockIdx.x < CHAN_BLOCKS) {
        const int plane4 = H * W / 4;
        int g0 = blockIdx.x * blockDim.x + threadIdx.x;
        #pragma unroll
        for (int k = 0; k < 4; k++) {
            int i = g0 + k * N4_STRIDE;
            int b = i / plane4;
            int p = i - b * plane4;
            const float4* xb = (const float4*)x + (size_t)b * 3 * plane4;
            float4 a = __ldg(xb + p);
            float4 c = __ldg(xb + p + plane4);
            float4 d = __ldg(xb + p + 2 * plane4);
            float4 r;
            r.x = a.x + c.x + d.x;
            r.y = a.y + c.y + d.y;
            r.z = a.z + c.z + d.z;
            r.w = a.w + c.w + d.w;
            ((float4*)g_xs)[i] = r;
        }
        return;
    }

    // ---- Gabor weights ----
    __shared__ float s_w[NF][228];
    __shared__ int sflag;
    int tid = threadIdx.x;
    int warp = tid >> 5;
    int lane = tid & 31;
    if (tid == 0) sflag = 0;

    if (warp < NF) {
        int f = warp;
        float th = theta[f];
        float sg = fmaxf(sigma[f], 1.0f);
        float lb = fmaxf(lambd[f], 2.0f);
        float gm = fminf(fmaxf(gamma[f], 0.1f), 1.0f);
        float ps = psi[f];
        float ct = cosf(th), st = sinf(th);
        const float TWO_PI = 6.283185307179586f;
        float inv_sg2 = 1.0f / (sg * sg);
        float gm2 = gm * gm;

        float vals[8];
        float sum = 0.0f;
        #pragma unroll
        for (int k = 0; k < 8; k++) {
            int i = lane + 32 * k;
            float v = 0.0f;
            if (i < KS * KS) {
                int hh = i / KS, ww = i % KS;
                float y = (float)(hh - PAD);
                float xx = (float)(ww - PAD);
                float xt = xx * ct + y * st;
                float yt = -xx * st + y * ct;
                float gaussian = expf(-0.5f * (xt * xt + gm2 * yt * yt) * inv_sg2);
                float sinus = cosf(TWO_PI * xt / lb + ps);
                v = gaussian * sinus;
            }
            vals[k] = v;
            sum += v;
        }
        #pragma unroll
        for (int o = 16; o; o >>= 1) sum += __shfl_xor_sync(0xffffffffu, sum, o);
        float mean = sum * (1.0f / 225.0f);

        float ss = 0.0f;
        #pragma unroll
        for (int k = 0; k < 8; k++) {
            int i = lane + 32 * k;
            if (i < KS * KS) {
                float d = vals[k] - mean;
                ss += d * d;
            }
        }
        #pragma unroll
        for (int o = 16; o; o >>= 1) ss += __shfl_xor_sync(0xffffffffu, ss, o);
        float inv = 1.0f / (sqrtf(ss * (1.0f / 224.0f)) + 1e-8f);

        #pragma unroll
        for (int k = 0; k < 8; k++) {
            int i = lane + 32 * k;
            if (i < KS * KS) s_w[f][i] = (vals[k] - mean) * inv;
        }
    }
    __syncthreads();

    for (int idx = tid; idx < KS * KS * NF; idx += 256) {
        int i = idx >> 3, f = idx & 7;
        g_w[idx] = s_w[f][i];
    }

    const int gf[5] = {0, 1, 2, 3, 4};
    const int gp[5] = {0, 7, 6, 5, 4};
    const float E = 1e-5f;
    int bad = 0;

    for (int idx = tid; idx < 245; idx += 256) {
        int q = idx / 5, g = idx % 5;
        int kyp = q / 7, kxp = q % 7;
        int i1 = kyp * 15 + kxp;
        int i2 = (14 - kyp) * 15 + (14 - kxp);
        int i3 = kyp * 15 + (14 - kxp);
        int i4 = (14 - kyp) * 15 + kxp;
        int f = gf[g], fp = gp[g];
        float f1 = s_w[f][i1], f2 = s_w[f][i2], f3 = s_w[f][i3], f4 = s_w[f][i4];
        float p1 = s_w[fp][i1], p2 = s_w[fp][i2], p3 = s_w[fp][i3], p4 = s_w[fp][i4];
        float af = 0.5f * (f1 + f2), bf = 0.5f * (f3 + f4);
        float ap = 0.5f * (p1 + p2), bp = 0.5f * (p3 + p4);
        float wpf = 0.5f * (af + bf), wmf = 0.5f * (af - bf);
        float wpp = 0.5f * (ap + bp), wmp = 0.5f * (ap - bp);
        float wp = 0.5f * (wpf + wpp), wm = 0.5f * (wmf - wmp);
        if (fabsf(f1 - f2) > E || fabsf(f3 - f4) > E ||
            fabsf(p1 - p2) > E || fabsf(p3 - p4) > E ||
            fabsf(wpf - wpp) > E || fabsf(wmf + wmp) > E) bad = 1;
        g_wq[q * 16 + 2 * g] = wp;
        g_wq[q * 16 + 2 * g + 1] = wp;
        if (g >= 1 && g <= 3) {
            g_wq[q * 16 + 10 + 2 * (g - 1)] = wm;
            g_wq[q * 16 + 10 + 2 * (g - 1) + 1] = wm;
        }
    }

    for (int idx = tid; idx < 35; idx += 256) {
        int kyp = idx / 5, g = idx % 5;
        int i1 = kyp * 15 + 7, i2 = (14 - kyp) * 15 + 7;
        int f = gf[g], fp = gp[g];
        float f1 = s_w[f][i1], f2 = s_w[f][i2];
        float p1 = s_w[fp][i1], p2 = s_w[fp][i2];
        float af = 0.5f * (f1 + f2), ap = 0.5f * (p1 + p2);
        float wp = 0.5f * (af + ap);
        if (fabsf(f1 - f2) > E || fabsf(p1 - p2) > E || fabsf(af - ap) > E) bad = 1;
        g_wq[WQ_COL + kyp * 10 + 2 * g] = wp;
        g_wq[WQ_COL + kyp * 10 + 2 * g + 1] = wp;
    }

    for (int idx = tid; idx < 35; idx += 256) {
        int kxp = idx / 5, g = idx % 5;
        int i1 = 105 + kxp, i3 = 105 + 14 - kxp;
        int f = gf[g], fp = gp[g];
        float f1 = s_w[f][i1], f3 = s_w[f][i3];
        float p1 = s_w[fp][i1], p3 = s_w[fp][i3];
        float af = 0.5f * (f1 + f3), ap = 0.5f * (p1 + p3);
        float wp = 0.5f * (af + ap);
        if (fabsf(f1 - f3) > E || fabsf(p1 - p3) > E || fabsf(af - ap) > E) bad = 1;
        g_wq[WQ_ROW + kxp * 10 + 2 * g] = wp;
        g_wq[WQ_ROW + kxp * 10 + 2 * g + 1] = wp;
    }

    if (tid < 5) {
        int g = tid;
        int f = gf[g], fp = gp[g];
        float f1 = s_w[f][112], p1 = s_w[fp][112];
        float wp = 0.5f * (f1 + p1);
        if (fabsf(f1 - p1) > E) bad = 1;
        g_wq[WQ_CEN + 2 * g] = wp;
        g_wq[WQ_CEN + 2 * g + 1] = wp;
    }

    if (bad) atomicOr(&sflag, 1);
    __syncthreads();
    if (tid == 0) g_flag = sflag;
}

// ---------------------------------------------------------------------------
// Conv: 4-fold symmetry, shifted packed windows, constant weights with
// explicit 128-bit constant loads (LDC.128 halves constant-port ops).
// Block (16,16), tile 64x16, 4 px/thread, 3 CTA/SM.
// ---------------------------------------------------------------------------
__global__ void __launch_bounds__(256, 3)
gabor_conv_sym(float* __restrict__ out) {
    __shared__ __align__(16) float s_in[SROWS * SSTRIDE];

    int txq = threadIdx.x;        // 0..15 -> 4 px each
    int tyr = threadIdx.y;        // 0..15
    int tid = txq + tyr * 16;
    int x0 = blockIdx.x * TILE_X;
    int y0 = blockIdx.y * TILE_Y;
    int b  = blockIdx.z;

    if (g_flag != 0) {
        // generic correct path (runs only if symmetry check failed)
        const float* xs = g_xs + (size_t)b * H * W;
        float* ob = out + (size_t)b * NF * H * W;
        int y = y0 + tyr;
        #pragma unroll 1
        for (int f = 0; f < NF; f++) {
            #pragma unroll 1
            for (int p = 0; p < 4; p++) {
                int px = x0 + txq * 4 + p;
                float acc = 0.0f;
                for (int ky = 0; ky < KS; ky++) {
                    int gy = y - PAD + ky;
                    if (gy < 0 || gy >= H) continue;
                    for (int kx = 0; kx < KS; kx++) {
                        int gx = px - PAD + kx;
                        if (gx < 0 || gx >= W) continue;
                        acc += g_w[(ky * KS + kx) * NF + f] * xs[gy * W + gx];
                    }
                }
                ob[f * H * W + y * W + px] = acc;
            }
        }
        return;
    }

    const float* xs = g_xs + (size_t)b * H * W;
    for (int i = tid; i < SROWS * SCOLS; i += 256) {
        int r = i / SCOLS, c = i - r * SCOLS;
        int gy = y0 - PAD + r;
        int gx = x0 - PAD + c;
        float v = 0.0f;
        if (gy >= 0 && gy < H && gx >= 0 && gx < W) v = xs[gy * W + gx];
        s_in[r * SSTRIDE + c] = v;
    }
    __syncthreads();

    int c0 = txq * 4;
    ull P[5][2], Q[3][2];
    #pragma unroll
    for (int g = 0; g < 5; g++) { P[g][0] = 0ull; P[g][1] = 0ull; }
    #pragma unroll
    for (int g = 0; g < 3; g++) { Q[g][0] = 0ull; Q[g][1] = 0ull; }

    #pragma unroll 1
    for (int kyp = 0; kyp < 7; kyp++) {
        const float4* tp = (const float4*)(s_in + (tyr + kyp) * SSTRIDE + c0);
        const float4* bp = (const float4*)(s_in + (tyr + 14 - kyp) * SSTRIDE + c0);

        // packed shifted windows
        ull tbP[17], tdP[17];
        #pragma unroll
        for (int j = 0; j < 5; j++) {
            float4 tv = tp[j];
            float4 bv = bp[j];
            ull t0 = pk(tv.x, tv.y), t1 = pk(tv.z, tv.w);
            ull b0 = pk(bv.x, bv.y), b1 = pk(bv.z, bv.w);
            tbP[4 * j] = add2(t0, b0);
            tdP[4 * j] = sub2(t0, b0);
            if (4 * j + 2 <= 16) {
                tbP[4 * j + 2] = add2(t1, b1);
                tdP[4 * j + 2] = sub2(t1, b1);
            }
        }
        #pragma unroll
        for (int k = 0; k < 8; k++) {
            float l0, h0, l1, h1;
            unpk(l0, h0, tbP[2 * k]); unpk(l1, h1, tbP[2 * k + 2]);
            tbP[2 * k + 1] = pk(h0, l1);
            unpk(l0, h0, tdP[2 * k]); unpk(l1, h1, tdP[2 * k + 2]);
            tdP[2 * k + 1] = pk(h0, l1);
        }

        const float* wq = c_wq + kyp * 112;
        #pragma unroll
        for (int kxp = 0; kxp < 7; kxp++) {
            // 64B-aligned quad weights: 4 x LDC.128 instead of 8 x LDC.64
            const ulonglong2* wv2 = (const ulonglong2*)(wq + kxp * 16);
            ulonglong2 wa = wv2[0], wb = wv2[1], wc2 = wv2[2], wd = wv2[3];
            ull w0 = wa.x, w1 = wa.y, w2 = wb.x, w3 = wb.y, w4 = wc2.x;
            ull m0 = wc2.y, m1 = wd.x, m2 = wd.y;
            #pragma unroll
            for (int pp = 0; pp < 2; pp++) {
                int o = 2 * pp;
                ull u = add2(tbP[o + kxp], tbP[o + 14 - kxp]);
                ull v = sub2(tdP[o + kxp], tdP[o + 14 - kxp]);
                fma2(P[0][pp], u, w0);
                fma2(P[1][pp], u, w1);
                fma2(P[2][pp], u, w2);
                fma2(P[3][pp], u, w3);
                fma2(P[4][pp], u, w4);
                fma2(Q[0][pp], v, m0);
                fma2(Q[1][pp], v, m1);
                fma2(Q[2][pp], v, m2);
            }
        }
        const ull* wc = (const ull*)(c_wq + WQ_COL + kyp * 10);
        ull c0w = wc[0], c1w = wc[1], c2w = wc[2], c3w = wc[3], c4w = wc[4];
        #pragma unroll
        for (int pp = 0; pp < 2; pp++) {
            ull u = tbP[2 * pp + 7];
            fma2(P[0][pp], u, c0w);
            fma2(P[1][pp], u, c1w);
            fma2(P[2][pp], u, c2w);
            fma2(P[3][pp], u, c3w);
            fma2(P[4][pp], u, c4w);
        }
    }

    // ky = 7 row
    {
        const float4* rp = (const float4*)(s_in + (tyr + 7) * SSTRIDE + c0);
        ull rP[17];
        float rf[20];
        #pragma unroll
        for (int j = 0; j < 5; j++) {
            float4 v = rp[j];
            rf[4 * j + 0] = v.x; rf[4 * j + 1] = v.y;
            rf[4 * j + 2] = v.z; rf[4 * j + 3] = v.w;
        }
        #pragma unroll
        for (int i = 0; i < 17; i++) rP[i] = pk(rf[i], rf[i + 1]);

        #pragma unroll
        for (int kxp = 0; kxp < 7; kxp++) {
            const ull* wr = (const ull*)(c_wq + WQ_ROW + kxp * 10);
            ull r0w = wr[0], r1w = wr[1], r2w = wr[2], r3w = wr[3], r4w = wr[4];
            #pragma unroll
            for (int pp = 0; pp < 2; pp++) {
                int o = 2 * pp;
                ull u = add2(rP[o + kxp], rP[o + 14 - kxp]);
                fma2(P[0][pp], u, r0w);
                fma2(P[1][pp], u, r1w);
                fma2(P[2][pp], u, r2w);
                fma2(P[3][pp], u, r3w);
                fma2(P[4][pp], u, r4w);
            }
        }
        const ull* wn = (const ull*)(c_wq + WQ_CEN);
        ull n0 = wn[0], n1 = wn[1], n2 = wn[2], n3 = wn[3], n4 = wn[4];
        #pragma unroll
        for (int pp = 0; pp < 2; pp++) {
            ull u = rP[2 * pp + 7];
            fma2(P[0][pp], u, n0);
            fma2(P[1][pp], u, n1);
            fma2(P[2][pp], u, n2);
            fma2(P[3][pp], u, n3);
            fma2(P[4][pp], u, n4);
        }
    }

    // epilogue
    float p[5][4], q[3][4];
    #pragma unroll
    for (int g = 0; g < 5; g++) {
        unpk(p[g][0], p[g][1], P[g][0]);
        unpk(p[g][2], p[g][3], P[g][1]);
    }
    #pragma unroll
    for (int g = 0; g < 3; g++) {
        unpk(q[g][0], q[g][1], Q[g][0]);
        unpk(q[g][2], q[g][3], Q[g][1]);
    }

    float r[8][4];
    #pragma unroll
    for (int px = 0; px < 4; px++) {
        r[0][px] = p[0][px];
        r[4][px] = p[4][px];
        r[1][px] = p[1][px] + q[0][px];
        r[7][px] = p[1][px] - q[0][px];
        r[2][px] = p[2][px] + q[1][px];
        r[6][px] = p[2][px] - q[1][px];
        r[3][px] = p[3][px] + q[2][px];
        r[5][px] = p[3][px] - q[2][px];
    }

    float* ob = out + (size_t)b * NF * H * W;
    int y = y0 + tyr;
    int xb = x0 + c0;
    #pragma unroll
    for (int f = 0; f < NF; f++) {
        float4 v = make_float4(r[f][0], r[f][1], r[f][2], r[f][3]);
        *(float4*)(ob + f * H * W + y * W + xb) = v;
    }
}

// ---------------------------------------------------------------------------
extern "C" void kernel_launch(void* const* d_in, const int* in_sizes, int n_in,
                              void* d_out, int out_size) {
    const float* x     = (const float*)d_in[0];
    const float* theta = (const float*)d_in[1];
    const float* sigma = (const float*)d_in[2];
    const float* lambd = (const float*)d_in[3];
    const float* gamma = (const float*)d_in[4];
    const float* psi   = (const float*)d_in[5];
    float* out = (float*)d_out;

    prep_kernel<<<CHAN_BLOCKS + 1, 256>>>(x, theta, sigma, lambd, gamma, psi);

    void* src = nullptr;
    cudaGetSymbolAddress(&src, g_wq);
    cudaMemcpyToSymbolAsync(c_wq, src, WQ_TOTAL * sizeof(float), 0,
                            cudaMemcpyDeviceToDevice, 0);

    dim3 blk(16, 16);
    dim3 grd(W / TILE_X, H / TILE_Y, BATCH);
    gabor_conv_sym<<<grd, blk>>>(out);
}

// round 12
// speedup vs baseline: 1.2779x; 1.0276x over previous
#include <cuda_runtime.h>

#define W 256
#define H 256
#define BATCH 64
#define NF 8
#define KS 15
#define PAD 7

#define TILE_X 64           // 16 threads x 4 px
#define TILE_Y 16
#define SROWS (TILE_Y + KS - 1)   // 30
#define SCOLS (TILE_X + KS - 1)   // 78
#define SSTRIDE 80

// derived-weight layout (floats, duplicated for f32x2 broadcast)
#define WQ_COL 784          // 49 quads * 16
#define WQ_ROW 854          // + 7*10
#define WQ_CEN 924          // + 7*10
#define WQ_TOTAL 934

#define CHAN_BLOCKS 512     // 8 float4-triples per thread (MLP ~24)
#define N4_STRIDE (CHAN_BLOCKS * 256)     // 131072

typedef unsigned long long ull;

__device__ float g_xs[BATCH * H * W];
__device__ float g_w[KS * KS * NF];    // full weights [tap][filter] (fallback)
__device__ float g_wq[WQ_TOTAL];       // staging for constant copy
__device__ int   g_flag;               // 1 -> symmetry violated, use fallback

__constant__ __align__(16) float c_wq[WQ_TOTAL];

__device__ __forceinline__ ull pk(float a, float b) {
    ull r; asm("mov.b64 %0, {%1, %2};" : "=l"(r) : "f"(a), "f"(b)); return r;
}
__device__ __forceinline__ ull add2(ull a, ull b) {
    ull r; asm("add.rn.f32x2 %0, %1, %2;" : "=l"(r) : "l"(a), "l"(b)); return r;
}
__device__ __forceinline__ ull sub2(ull a, ull b) {
    ull r; asm("sub.rn.f32x2 %0, %1, %2;" : "=l"(r) : "l"(a), "l"(b)); return r;
}
__device__ __forceinline__ void fma2(ull& acc, ull a, ull b) {
    asm("fma.rn.f32x2 %0, %1, %2, %0;" : "+l"(acc) : "l"(a), "l"(b));
}
__device__ __forceinline__ void unpk(float& lo, float& hi, ull v) {
    asm("mov.b64 {%0, %1}, %2;" : "=f"(lo), "=f"(hi) : "l"(v));
}

// ---------------------------------------------------------------------------
// Prep: blocks [0, CHAN_BLOCKS) channel-sum (8 float4s/thread, MLP~24);
// block CHAN_BLOCKS builds the Gabor + derived weights.
// ---------------------------------------------------------------------------
__global__ void prep_kernel(const float* __restrict__ x,
                            const float* __restrict__ theta,
                            const float* __restrict__ sigma,
                            const float* __restrict__ lambd,
                            const float* __restrict__ gamma,
                            const float* __restrict__ psi) {
    if (blockIdx.x < CHAN_BLOCKS) {
        const int plane4 = H * W / 4;
        int g0 = blockIdx.x * blockDim.x + threadIdx.x;
        #pragma unroll
        for (int k = 0; k < 8; k++) {
            int i = g0 + k * N4_STRIDE;
            int b = i / plane4;
            int p = i - b * plane4;
            const float4* xb = (const float4*)x + (size_t)b * 3 * plane4;
            float4 a = __ldg(xb + p);
            float4 c = __ldg(xb + p + plane4);
            float4 d = __ldg(xb + p + 2 * plane4);
            float4 r;
            r.x = a.x + c.x + d.x;
            r.y = a.y + c.y + d.y;
            r.z = a.z + c.z + d.z;
            r.w = a.w + c.w + d.w;
            ((float4*)g_xs)[i] = r;
        }
        return;
    }

    // ---- Gabor weights ----
    __shared__ float s_w[NF][228];
    __shared__ int sflag;
    int tid = threadIdx.x;
    int warp = tid >> 5;
    int lane = tid & 31;
    if (tid == 0) sflag = 0;

    if (warp < NF) {
        int f = warp;
        float th = theta[f];
        float sg = fmaxf(sigma[f], 1.0f);
        float lb = fmaxf(lambd[f], 2.0f);
        float gm = fminf(fmaxf(gamma[f], 0.1f), 1.0f);
        float ps = psi[f];
        float ct = cosf(th), st = sinf(th);
        const float TWO_PI = 6.283185307179586f;
        float inv_sg2 = 1.0f / (sg * sg);
        float gm2 = gm * gm;

        float vals[8];
        float sum = 0.0f;
        #pragma unroll
        for (int k = 0; k < 8; k++) {
            int i = lane + 32 * k;
            float v = 0.0f;
            if (i < KS * KS) {
                int hh = i / KS, ww = i % KS;
                float y = (float)(hh - PAD);
                float xx = (float)(ww - PAD);
                float xt = xx * ct + y * st;
                float yt = -xx * st + y * ct;
                float gaussian = expf(-0.5f * (xt * xt + gm2 * yt * yt) * inv_sg2);
                float sinus = cosf(TWO_PI * xt / lb + ps);
                v = gaussian * sinus;
            }
            vals[k] = v;
            sum += v;
        }
        #pragma unroll
        for (int o = 16; o; o >>= 1) sum += __shfl_xor_sync(0xffffffffu, sum, o);
        float mean = sum * (1.0f / 225.0f);

        float ss = 0.0f;
        #pragma unroll
        for (int k = 0; k < 8; k++) {
            int i = lane + 32 * k;
            if (i < KS * KS) {
                float d = vals[k] - mean;
                ss += d * d;
            }
        }
        #pragma unroll
        for (int o = 16; o; o >>= 1) ss += __shfl_xor_sync(0xffffffffu, ss, o);
        float inv = 1.0f / (sqrtf(ss * (1.0f / 224.0f)) + 1e-8f);

        #pragma unroll
        for (int k = 0; k < 8; k++) {
            int i = lane + 32 * k;
            if (i < KS * KS) s_w[f][i] = (vals[k] - mean) * inv;
        }
    }
    __syncthreads();

    for (int idx = tid; idx < KS * KS * NF; idx += 256) {
        int i = idx >> 3, f = idx & 7;
        g_w[idx] = s_w[f][i];
    }

    const int gf[5] = {0, 1, 2, 3, 4};
    const int gp[5] = {0, 7, 6, 5, 4};
    const float E = 1e-5f;
    int bad = 0;

    for (int idx = tid; idx < 245; idx += 256) {
        int q = idx / 5, g = idx % 5;
        int kyp = q / 7, kxp = q % 7;
        int i1 = kyp * 15 + kxp;
        int i2 = (14 - kyp) * 15 + (14 - kxp);
        int i3 = kyp * 15 + (14 - kxp);
        int i4 = (14 - kyp) * 15 + kxp;
        int f = gf[g], fp = gp[g];
        float f1 = s_w[f][i1], f2 = s_w[f][i2], f3 = s_w[f][i3], f4 = s_w[f][i4];
        float p1 = s_w[fp][i1], p2 = s_w[fp][i2], p3 = s_w[fp][i3], p4 = s_w[fp][i4];
        float af = 0.5f * (f1 + f2), bf = 0.5f * (f3 + f4);
        float ap = 0.5f * (p1 + p2), bp = 0.5f * (p3 + p4);
        float wpf = 0.5f * (af + bf), wmf = 0.5f * (af - bf);
        float wpp = 0.5f * (ap + bp), wmp = 0.5f * (ap - bp);
        float wp = 0.5f * (wpf + wpp), wm = 0.5f * (wmf - wmp);
        if (fabsf(f1 - f2) > E || fabsf(f3 - f4) > E ||
            fabsf(p1 - p2) > E || fabsf(p3 - p4) > E ||
            fabsf(wpf - wpp) > E || fabsf(wmf + wmp) > E) bad = 1;
        g_wq[q * 16 + 2 * g] = wp;
        g_wq[q * 16 + 2 * g + 1] = wp;
        if (g >= 1 && g <= 3) {
            g_wq[q * 16 + 10 + 2 * (g - 1)] = wm;
            g_wq[q * 16 + 10 + 2 * (g - 1) + 1] = wm;
        }
    }

    for (int idx = tid; idx < 35; idx += 256) {
        int kyp = idx / 5, g = idx % 5;
        int i1 = kyp * 15 + 7, i2 = (14 - kyp) * 15 + 7;
        int f = gf[g], fp = gp[g];
        float f1 = s_w[f][i1], f2 = s_w[f][i2];
        float p1 = s_w[fp][i1], p2 = s_w[fp][i2];
        float af = 0.5f * (f1 + f2), ap = 0.5f * (p1 + p2);
        float wp = 0.5f * (af + ap);
        if (fabsf(f1 - f2) > E || fabsf(p1 - p2) > E || fabsf(af - ap) > E) bad = 1;
        g_wq[WQ_COL + kyp * 10 + 2 * g] = wp;
        g_wq[WQ_COL + kyp * 10 + 2 * g + 1] = wp;
    }

    for (int idx = tid; idx < 35; idx += 256) {
        int kxp = idx / 5, g = idx % 5;
        int i1 = 105 + kxp, i3 = 105 + 14 - kxp;
        int f = gf[g], fp = gp[g];
        float f1 = s_w[f][i1], f3 = s_w[f][i3];
        float p1 = s_w[fp][i1], p3 = s_w[fp][i3];
        float af = 0.5f * (f1 + f3), ap = 0.5f * (p1 + p3);
        float wp = 0.5f * (af + ap);
        if (fabsf(f1 - f3) > E || fabsf(p1 - p3) > E || fabsf(af - ap) > E) bad = 1;
        g_wq[WQ_ROW + kxp * 10 + 2 * g] = wp;
        g_wq[WQ_ROW + kxp * 10 + 2 * g + 1] = wp;
    }

    if (tid < 5) {
        int g = tid;
        int f = gf[g], fp = gp[g];
        float f1 = s_w[f][112], p1 = s_w[fp][112];
        float wp = 0.5f * (f1 + p1);
        if (fabsf(f1 - p1) > E) bad = 1;
        g_wq[WQ_CEN + 2 * g] = wp;
        g_wq[WQ_CEN + 2 * g + 1] = wp;
    }

    if (bad) atomicOr(&sflag, 1);
    __syncthreads();
    if (tid == 0) g_flag = sflag;
}

// ---------------------------------------------------------------------------
// Conv: 4-fold symmetry, shifted packed windows, constant weights.
// Flag load overlapped with tile load; ky=7 row hoisted before kyp loop.
// Block (16,16), tile 64x16, 4 px/thread, 3 CTA/SM.
// ---------------------------------------------------------------------------
__global__ void __launch_bounds__(256, 3)
gabor_conv_sym(float* __restrict__ out) {
    __shared__ __align__(16) float s_in[SROWS * SSTRIDE];

    int txq = threadIdx.x;        // 0..15 -> 4 px each
    int tyr = threadIdx.y;        // 0..15
    int tid = txq + tyr * 16;
    int x0 = blockIdx.x * TILE_X;
    int y0 = blockIdx.y * TILE_Y;
    int b  = blockIdx.z;

    // issue the flag load early; tile load proceeds unconditionally (both
    // paths read g_xs), branch resolves after the barrier.
    int flag = g_flag;

    const float* xs = g_xs + (size_t)b * H * W;
    for (int i = tid; i < SROWS * SCOLS; i += 256) {
        int r = i / SCOLS, c = i - r * SCOLS;
        int gy = y0 - PAD + r;
        int gx = x0 - PAD + c;
        float v = 0.0f;
        if (gy >= 0 && gy < H && gx >= 0 && gx < W) v = xs[gy * W + gx];
        s_in[r * SSTRIDE + c] = v;
    }
    __syncthreads();

    if (flag != 0) {
        // generic correct path (runs only if symmetry check failed)
        float* ob = out + (size_t)b * NF * H * W;
        int y = y0 + tyr;
        #pragma unroll 1
        for (int f = 0; f < NF; f++) {
            #pragma unroll 1
            for (int p = 0; p < 4; p++) {
                int px = x0 + txq * 4 + p;
                float acc = 0.0f;
                for (int ky = 0; ky < KS; ky++) {
                    int gy = y - PAD + ky;
                    if (gy < 0 || gy >= H) continue;
                    for (int kx = 0; kx < KS; kx++) {
                        int gx = px - PAD + kx;
                        if (gx < 0 || gx >= W) continue;
                        acc += g_w[(ky * KS + kx) * NF + f] * xs[gy * W + gx];
                    }
                }
                ob[f * H * W + y * W + px] = acc;
            }
        }
        return;
    }

    int c0 = txq * 4;
    ull P[5][2], Q[3][2];
    #pragma unroll
    for (int g = 0; g < 5; g++) { P[g][0] = 0ull; P[g][1] = 0ull; }
    #pragma unroll
    for (int g = 0; g < 3; g++) { Q[g][0] = 0ull; Q[g][1] = 0ull; }

    // ky = 7 row first (issues LDS early, smaller live set)
    {
        const float4* rp = (const float4*)(s_in + (tyr + 7) * SSTRIDE + c0);
        ull rP[17];
        float rf[20];
        #pragma unroll
        for (int j = 0; j < 5; j++) {
            float4 v = rp[j];
            rf[4 * j + 0] = v.x; rf[4 * j + 1] = v.y;
            rf[4 * j + 2] = v.z; rf[4 * j + 3] = v.w;
        }
        #pragma unroll
        for (int i = 0; i < 17; i++) rP[i] = pk(rf[i], rf[i + 1]);

        #pragma unroll
        for (int kxp = 0; kxp < 7; kxp++) {
            const ull* wr = (const ull*)(c_wq + WQ_ROW + kxp * 10);
            ull r0w = wr[0], r1w = wr[1], r2w = wr[2], r3w = wr[3], r4w = wr[4];
            #pragma unroll
            for (int pp = 0; pp < 2; pp++) {
                int o = 2 * pp;
                ull u = add2(rP[o + kxp], rP[o + 14 - kxp]);
                fma2(P[0][pp], u, r0w);
                fma2(P[1][pp], u, r1w);
                fma2(P[2][pp], u, r2w);
                fma2(P[3][pp], u, r3w);
                fma2(P[4][pp], u, r4w);
            }
        }
        const ull* wn = (const ull*)(c_wq + WQ_CEN);
        ull n0 = wn[0], n1 = wn[1], n2 = wn[2], n3 = wn[3], n4 = wn[4];
        #pragma unroll
        for (int pp = 0; pp < 2; pp++) {
            ull u = rP[2 * pp + 7];
            fma2(P[0][pp], u, n0);
            fma2(P[1][pp], u, n1);
            fma2(P[2][pp], u, n2);
            fma2(P[3][pp], u, n3);
            fma2(P[4][pp], u, n4);
        }
    }

    #pragma unroll 1
    for (int kyp = 0; kyp < 7; kyp++) {
        const float4* tp = (const float4*)(s_in + (tyr + kyp) * SSTRIDE + c0);
        const float4* bp = (const float4*)(s_in + (tyr + 14 - kyp) * SSTRIDE + c0);

        // packed shifted windows
        ull tbP[17], tdP[17];
        #pragma unroll
        for (int j = 0; j < 5; j++) {
            float4 tv = tp[j];
            float4 bv = bp[j];
            ull t0 = pk(tv.x, tv.y), t1 = pk(tv.z, tv.w);
            ull b0 = pk(bv.x, bv.y), b1 = pk(bv.z, bv.w);
            tbP[4 * j] = add2(t0, b0);
            tdP[4 * j] = sub2(t0, b0);
            if (4 * j + 2 <= 16) {
                tbP[4 * j + 2] = add2(t1, b1);
                tdP[4 * j + 2] = sub2(t1, b1);
            }
        }
        #pragma unroll
        for (int k = 0; k < 8; k++) {
            float l0, h0, l1, h1;
            unpk(l0, h0, tbP[2 * k]); unpk(l1, h1, tbP[2 * k + 2]);
            tbP[2 * k + 1] = pk(h0, l1);
            unpk(l0, h0, tdP[2 * k]); unpk(l1, h1, tdP[2 * k + 2]);
            tdP[2 * k + 1] = pk(h0, l1);
        }

        const float* wq = c_wq + kyp * 112;
        #pragma unroll
        for (int kxp = 0; kxp < 7; kxp++) {
            const ulonglong2* wv2 = (const ulonglong2*)(wq + kxp * 16);
            ulonglong2 wa = wv2[0], wb = wv2[1], wc2 = wv2[2], wd = wv2[3];
            ull w0 = wa.x, w1 = wa.y, w2 = wb.x, w3 = wb.y, w4 = wc2.x;
            ull m0 = wc2.y, m1 = wd.x, m2 = wd.y;
            #pragma unroll
            for (int pp = 0; pp < 2; pp++) {
                int o = 2 * pp;
                ull u = add2(tbP[o + kxp], tbP[o + 14 - kxp]);
                ull v = sub2(tdP[o + kxp], tdP[o + 14 - kxp]);
                fma2(P[0][pp], u, w0);
                fma2(P[1][pp], u, w1);
                fma2(P[2][pp], u, w2);
                fma2(P[3][pp], u, w3);
                fma2(P[4][pp], u, w4);
                fma2(Q[0][pp], v, m0);
                fma2(Q[1][pp], v, m1);
                fma2(Q[2][pp], v, m2);
            }
        }
        const ull* wc = (const ull*)(c_wq + WQ_COL + kyp * 10);
        ull c0w = wc[0], c1w = wc[1], c2w = wc[2], c3w = wc[3], c4w = wc[4];
        #pragma unroll
        for (int pp = 0; pp < 2; pp++) {
            ull u = tbP[2 * pp + 7];
            fma2(P[0][pp], u, c0w);
            fma2(P[1][pp], u, c1w);
            fma2(P[2][pp], u, c2w);
            fma2(P[3][pp], u, c3w);
            fma2(P[4][pp], u, c4w);
        }
    }

    // epilogue
    float p[5][4], q[3][4];
    #pragma unroll
    for (int g = 0; g < 5; g++) {
        unpk(p[g][0], p[g][1], P[g][0]);
        unpk(p[g][2], p[g][3], P[g][1]);
    }
    #pragma unroll
    for (int g = 0; g < 3; g++) {
        unpk(q[g][0], q[g][1], Q[g][0]);
        unpk(q[g][2], q[g][3], Q[g][1]);
    }

    float r[8][4];
    #pragma unroll
    for (int px = 0; px < 4; px++) {
        r[0][px] = p[0][px];
        r[4][px] = p[4][px];
        r[1][px] = p[1][px] + q[0][px];
        r[7][px] = p[1][px] - q[0][px];
        r[2][px] = p[2][px] + q[1][px];
        r[6][px] = p[2][px] - q[1][px];
        r[3][px] = p[3][px] + q[2][px];
        r[5][px] = p[3][px] - q[2][px];
    }

    float* ob = out + (size_t)b * NF * H * W;
    int y = y0 + tyr;
    int xb = x0 + c0;
    #pragma unroll
    for (int f = 0; f < NF; f++) {
        float4 v = make_float4(r[f][0], r[f][1], r[f][2], r[f][3]);
        *(float4*)(ob + f * H * W + y * W + xb) = v;
    }
}

// ---------------------------------------------------------------------------
extern "C" void kernel_launch(void* const* d_in, const int* in_sizes, int n_in,
                              void* d_out, int out_size) {
    const float* x     = (const float*)d_in[0];
    const float* theta = (const float*)d_in[1];
    const float* sigma = (const float*)d_in[2];
    const float* lambd = (const float*)d_in[3];
    const float* gamma = (const float*)d_in[4];
    const float* psi   = (const float*)d_in[5];
    float* out = (float*)d_out;

    prep_kernel<<<CHAN_BLOCKS + 1, 256>>>(x, theta, sigma, lambd, gamma, psi);

    void* src = nullptr;
    cudaGetSymbolAddress(&src, g_wq);
    cudaMemcpyToSymbolAsync(c_wq, src, WQ_TOTAL * sizeof(float), 0,
                            cudaMemcpyDeviceToDevice, 0);

    dim3 blk(16, 16);
    dim3 grd(W / TILE_X, H / TILE_Y, BATCH);
    gabor_conv_sym<<<grd, blk>>>(out);
}